// round 8
// baseline (speedup 1.0000x reference)
#include <cuda_runtime.h>
#include <cstdint>

// ---------------- problem shapes (fixed by the dataset) ----------------
constexpr int B    = 8;
constexpr int C    = 19;
constexpr int H    = 512;
constexpr int W    = 1024;
constexpr int HW   = H * W;            // 524288 = 2^19
constexpr int NPIX = B * HW;           // 4194304
constexpr int Hh   = 128;
constexpr int Wh   = 256;
constexpr int HhWh = Hh * Wh;          // 32768
constexpr int NHEAT = B * HhWh;        // 262144
constexpr int NBOX  = 8 * 64;          // 512

constexpr float OHEM_THRESH = 0.22314355513142097f;  // -log(0.8)
constexpr int   NBINS = 4096;
constexpr float BIN_SCALE = (float)NBINS / OHEM_THRESH;
constexpr float F32_TINY = 1.17549435e-38f;
constexpr float L2E  = 1.4426950408889634f;   // log2(e)
constexpr float LN2  = 0.6931471805599453f;   // ln(2)

constexpr int THREADS     = 256;
constexpr int TILE_PIX    = 512;                      // pixels per OHEM block
constexpr int TILE_BYTES  = TILE_PIX * 4;             // 2048 B per channel stage
constexpr int TILES_PER_IMG = HW / TILE_PIX;          // 1024
constexpr int OHEM_BLOCKS  = NPIX / TILE_PIX;         // 8192
constexpr int FOCAL_BLOCKS = NHEAT / (THREADS * 4);   // 256
constexpr int TOTAL_BLOCKS = OHEM_BLOCKS + FOCAL_BLOCKS + 1;  // 8449

// ---------------- device accumulators (zero at load; final block re-zeros
// them each run so graph replays stay deterministic) ----------------
__device__ double             g_sum_hard;
__device__ unsigned long long g_cnt_hard;
__device__ unsigned long long g_cnt_valid;
__device__ double             g_hist_sum[NBINS];
__device__ unsigned int       g_hist_cnt[NBINS];
__device__ double             g_pos_loss;
__device__ double             g_neg_loss;
__device__ double             g_npos;
__device__ double             g_reg_sum;
__device__ unsigned int       g_done;

__device__ __forceinline__ float ex2f(float x) {
    float r;
    asm("ex2.approx.ftz.f32 %0, %1;" : "=f"(r) : "f"(x));
    return r;
}
__device__ __forceinline__ float lg2f(float x) {
    float r;
    asm("lg2.approx.ftz.f32 %0, %1;" : "=f"(r) : "f"(x));
    return r;
}
__device__ __forceinline__ uint32_t smem_u32(const void* p) {
    uint32_t a;
    asm("{ .reg .u64 t; cvta.to.shared.u64 t, %1; cvt.u32.u64 %0, t; }" : "=r"(a) : "l"(p));
    return a;
}
__device__ __forceinline__ void mbar_init(uint32_t mbar, uint32_t count) {
    asm volatile("mbarrier.init.shared.b64 [%0], %1;" :: "r"(mbar), "r"(count) : "memory");
}
__device__ __forceinline__ void mbar_expect_tx(uint32_t mbar, uint32_t bytes) {
    asm volatile("mbarrier.arrive.expect_tx.shared.b64 _, [%0], %1;"
                 :: "r"(mbar), "r"(bytes) : "memory");
}
__device__ __forceinline__ void bulk_g2s(uint32_t dst, const void* src,
                                         uint32_t bytes, uint32_t mbar) {
    asm volatile(
        "cp.async.bulk.shared::cluster.global.mbarrier::complete_tx::bytes [%0], [%1], %2, [%3];"
        :: "r"(dst), "l"(src), "r"(bytes), "r"(mbar) : "memory");
}
__device__ __forceinline__ void mbar_wait(uint32_t mbar, uint32_t phase) {
    uint32_t done;
    asm volatile(
        "{\n\t.reg .pred p;\n\t"
        "mbarrier.try_wait.parity.acquire.cta.shared::cta.b64 p, [%1], %2;\n\t"
        "selp.b32 %0, 1, 0, p;\n\t}"
        : "=r"(done) : "r"(mbar), "r"(phase) : "memory");
    while (!done) {
        asm volatile(
            "{\n\t.reg .pred p;\n\t"
            "mbarrier.try_wait.parity.acquire.cta.shared::cta.b64 p, [%1], %2, 0x989680;\n\t"
            "selp.b32 %0, 1, 0, p;\n\t}"
            : "=r"(done) : "r"(mbar), "r"(phase) : "memory");
    }
}

// ---------------- one fused kernel ----------------
__global__ __launch_bounds__(THREADS) void fused_loss_kernel(
    const float* __restrict__ seg,     const int*   __restrict__ masks,
    const float* __restrict__ hm_pred, const float* __restrict__ hm_tgt,
    const float* __restrict__ wh,      const float* __restrict__ bboxes,
    const int*   __restrict__ ct,      float* __restrict__ out)
{
    const int bid  = blockIdx.x;
    const int tid  = threadIdx.x;
    const int lane = tid & 31, wid = tid >> 5;

    __shared__ alignas(16) float              s_stage[C][TILE_PIX];  // 38912 B
    __shared__ alignas(8)  unsigned long long s_mbar[C];
    __shared__ float    s_f0[8], s_f1[8], s_f2[8];
    __shared__ unsigned s_u0[8], s_u1[8];

    if (bid < OHEM_BLOCKS) {
        // ====== OHEM CE: TMA-fed tile, 2 pixels/thread, streaming softmax ======
        int b    = bid >> 10;                 // / TILES_PER_IMG
        int tile = bid & (TILES_PER_IMG - 1);
        int pix0 = tile * TILE_PIX;
        const float* img = seg + (size_t)b * C * HW;

        // init barriers, then issue all 19 channel copies upfront
        if (tid == 0) {
            #pragma unroll
            for (int c = 0; c < C; c++)
                mbar_init(smem_u32(&s_mbar[c]), 1);
        }
        __syncthreads();
        if (tid == 0) {
            #pragma unroll
            for (int c = 0; c < C; c++) {
                uint32_t mb = smem_u32(&s_mbar[c]);
                mbar_expect_tx(mb, TILE_BYTES);
                bulk_g2s(smem_u32(&s_stage[c][0]), img + (size_t)c * HW + pix0,
                         TILE_BYTES, mb);
            }
        }

        // mask for this thread's 2 pixels (coalesced LDG, streaming)
        int2 tt = __ldcs((const int2*)masks + (size_t)bid * (TILE_PIX / 2) + tid);
        bool valid0 = (tt.x != 255), valid1 = (tt.y != 255);
        int t0 = tt.x, t1 = tt.y;

        float s0 = 0.0f, s1 = 0.0f, xt0 = 0.0f, xt1 = 0.0f;
        #pragma unroll
        for (int c = 0; c < C; c++) {
            mbar_wait(smem_u32(&s_mbar[c]), 0);
            float2 v = *(const float2*)&s_stage[c][tid * 2];
            s0 += ex2f(v.x * L2E);
            s1 += ex2f(v.y * L2E);
            xt0 = (c == t0) ? v.x : xt0;
            xt1 = (c == t1) ? v.y : xt1;
        }

        float ce0 = valid0 ? __fmaf_rn(lg2f(s0), LN2, -xt0) : 0.0f;
        float ce1 = valid1 ? __fmaf_rn(lg2f(s1), LN2, -xt1) : 0.0f;
        bool h0 = ce0 > OHEM_THRESH, h1 = ce1 > OHEM_THRESH;

        // rare path: ce <= THRESH -> global histogram (expected ~handful of hits)
        if (!h0) {
            int bin = min(max((int)(ce0 * BIN_SCALE), 0), NBINS - 1);
            atomicAdd(&g_hist_cnt[bin], 1u);
            atomicAdd(&g_hist_sum[bin], (double)ce0);
        }
        if (!h1) {
            int bin = min(max((int)(ce1 * BIN_SCALE), 0), NBINS - 1);
            atomicAdd(&g_hist_cnt[bin], 1u);
            atomicAdd(&g_hist_sum[bin], (double)ce1);
        }

        float    fs = (h0 ? ce0 : 0.0f) + (h1 ? ce1 : 0.0f);
        unsigned hc = (unsigned)h0 + (unsigned)h1;
        unsigned vc = (unsigned)valid0 + (unsigned)valid1;
        #pragma unroll
        for (int o = 16; o > 0; o >>= 1) {
            fs += __shfl_xor_sync(0xffffffffu, fs, o);
            hc += __shfl_xor_sync(0xffffffffu, hc, o);
            vc += __shfl_xor_sync(0xffffffffu, vc, o);
        }
        if (lane == 0) { s_f0[wid] = fs; s_u0[wid] = hc; s_u1[wid] = vc; }
        __syncthreads();
        if (tid == 0) {
            double ts = 0.0; unsigned th = 0, tv = 0;
            #pragma unroll
            for (int i = 0; i < 8; i++) { ts += (double)s_f0[i]; th += s_u0[i]; tv += s_u1[i]; }
            atomicAdd(&g_sum_hard, ts);
            atomicAdd(&g_cnt_hard, (unsigned long long)th);
            atomicAdd(&g_cnt_valid, (unsigned long long)tv);
        }
    } else if (bid < OHEM_BLOCKS + FOCAL_BLOCKS) {
        // ============ focal: 4 elems per thread via float4 ============
        int i4 = (bid - OHEM_BLOCKS) * THREADS + tid;
        float4 pv  = __ldcs((const float4*)hm_pred + i4);
        float4 tv4 = __ldcs((const float4*)hm_tgt + i4);

        float pl = 0.0f, nl = 0.0f, np = 0.0f;
        const float* pp = &pv.x;
        const float* tp = &tv4.x;
        #pragma unroll
        for (int k = 0; k < 4; k++) {
            float p = fmaxf(pp[k], F32_TINY);
            float t = tp[k];
            if (t == 1.0f) {
                float om = 1.0f - p;
                pl += lg2f(p) * LN2 * om * om;
                np += 1.0f;
            } else {
                float omt = 1.0f - t;
                float wgt = omt * omt; wgt *= wgt;
                nl += lg2f(1.0f - p + F32_TINY) * LN2 * p * p * wgt;
            }
        }
        #pragma unroll
        for (int o = 16; o > 0; o >>= 1) {
            pl += __shfl_xor_sync(0xffffffffu, pl, o);
            nl += __shfl_xor_sync(0xffffffffu, nl, o);
            np += __shfl_xor_sync(0xffffffffu, np, o);
        }
        if (lane == 0) { s_f0[wid] = pl; s_f1[wid] = nl; s_f2[wid] = np; }
        __syncthreads();
        if (tid == 0) {
            double tpd = 0, tnd = 0, tcd = 0;
            #pragma unroll
            for (int k = 0; k < 8; k++) { tpd += (double)s_f0[k]; tnd += (double)s_f1[k]; tcd += (double)s_f2[k]; }
            atomicAdd(&g_pos_loss, tpd);
            atomicAdd(&g_neg_loss, tnd);
            atomicAdd(&g_npos, tcd);
        }
    } else {
        // ============ L1 regression (512 boxes, 2 per thread) ============
        float l1 = 0.0f;
        #pragma unroll
        for (int r = 0; r < 2; r++) {
            int i = tid + r * THREADS;
            int b = i >> 6;
            int x = ct[i * 2 + 0];
            int y = ct[i * 2 + 1];
            const float* whb = wh + (size_t)b * 2 * HhWh;
            float v0 = whb[y * Wh + x];
            float v1 = whb[HhWh + y * Wh + x];
            const float* bb = bboxes + (size_t)i * 4;
            float w = bb[2] - bb[0];
            float h = bb[3] - bb[1];
            l1 += fabsf(v0 - w) + fabsf(v1 - h);
        }
        #pragma unroll
        for (int o = 16; o > 0; o >>= 1) l1 += __shfl_xor_sync(0xffffffffu, l1, o);
        if (lane == 0) s_f0[wid] = l1;
        __syncthreads();
        if (tid == 0) {
            double tot = 0.0;
            #pragma unroll
            for (int k = 0; k < 8; k++) tot += (double)s_f0[k];
            g_reg_sum = tot;
        }
    }

    // ===================== last-block election =====================
    __shared__ bool s_last;
    __syncthreads();
    if (tid == 0) {
        __threadfence();
        unsigned prev = atomicAdd(&g_done, 1u);
        s_last = (prev == (unsigned)(TOTAL_BLOCKS - 1));
    }
    __syncthreads();
    if (!s_last) return;
    __threadfence();

    __shared__ float s_out[4];
    if (tid == 0) {
        // classification (OHEM)
        unsigned long long nmin = g_cnt_valid / 16ull;
        double k, top;
        if (g_cnt_hard >= nmin) {
            k = (double)g_cnt_hard;
            top = g_sum_hard;
        } else {
            k = (double)nmin;
            top = g_sum_hard;
            double need = (double)(nmin - g_cnt_hard);
            for (int bin = NBINS - 1; bin >= 0 && need > 0.0; --bin) {
                unsigned c = g_hist_cnt[bin];
                if (!c) continue;
                if ((double)c <= need) { top += g_hist_sum[bin]; need -= (double)c; }
                else                   { top += g_hist_sum[bin] * (need / (double)c); need = 0.0; }
            }
        }
        float cls = (k > 0.0) ? (float)(top / k) : 0.0f;

        // centerness (focal)
        double npos = g_npos;
        double fl = (npos == 0.0) ? -g_neg_loss
                                  : -(g_pos_loss + g_neg_loss) / fmax(npos, 1.0);
        float centerness = (float)fl;

        // bbox
        float regression = (float)g_reg_sum * 0.7f;
        float bbox = regression / ((float)NBOX + 1e-7f) * 0.1f;
        float localization = (centerness + bbox) * 1.0f;

        s_out[0] = cls;
        s_out[1] = localization;
        s_out[2] = centerness;
        s_out[3] = bbox;
    }
    __syncthreads();

    if (tid < 4) out[tid] = s_out[tid];
    for (int bin = tid; bin < NBINS; bin += THREADS) {
        g_hist_sum[bin] = 0.0;
        g_hist_cnt[bin] = 0u;
    }
    if (tid == 0) {
        g_sum_hard = 0.0; g_cnt_hard = 0ull; g_cnt_valid = 0ull;
        g_pos_loss = 0.0; g_neg_loss = 0.0; g_npos = 0.0; g_reg_sum = 0.0;
        __threadfence();
        g_done = 0u;
    }
}

// ---------------- launch ----------------
extern "C" void kernel_launch(void* const* d_in, const int* in_sizes, int n_in,
                              void* d_out, int out_size)
{
    const float* seg     = (const float*)d_in[0];
    const int*   masks   = (const int*)  d_in[1];
    const float* hm_pred = (const float*)d_in[2];
    const float* hm_tgt  = (const float*)d_in[3];
    const float* wh      = (const float*)d_in[4];
    const float* bboxes  = (const float*)d_in[5];
    // d_in[6] = labels (unused by the reference loss)
    const int*   ct      = (const int*)  d_in[7];
    float* out = (float*)d_out;

    fused_loss_kernel<<<TOTAL_BLOCKS, THREADS>>>(
        seg, masks, hm_pred, hm_tgt, wh, bboxes, ct, out);
}

// round 9
// speedup vs baseline: 1.3811x; 1.3811x over previous
#include <cuda_runtime.h>
#include <cstdint>

// ---------------- problem shapes (fixed by the dataset) ----------------
constexpr int B    = 8;
constexpr int C    = 19;
constexpr int H    = 512;
constexpr int W    = 1024;
constexpr int HW   = H * W;            // 524288 = 2^19
constexpr int NPIX = B * HW;           // 4194304
constexpr int Hh   = 128;
constexpr int Wh   = 256;
constexpr int HhWh = Hh * Wh;          // 32768
constexpr int NHEAT = B * HhWh;        // 262144
constexpr int NBOX  = 8 * 64;          // 512

constexpr float OHEM_THRESH = 0.22314355513142097f;  // -log(0.8)
constexpr int   NBINS = 4096;
constexpr float BIN_SCALE = (float)NBINS / OHEM_THRESH;
constexpr float F32_TINY = 1.17549435e-38f;
constexpr float L2E  = 1.4426950408889634f;   // log2(e)
constexpr float LN2  = 0.6931471805599453f;   // ln(2)

constexpr int THREADS      = 256;
constexpr int PIX_PER_THR  = 8;                               // 2 x float4
constexpr int TILE_PIX     = THREADS * PIX_PER_THR;           // 2048
constexpr int TILES_PER_IMG = HW / TILE_PIX;                  // 256
constexpr int OHEM_BLOCKS  = NPIX / TILE_PIX;                 // 2048
constexpr int FOCAL_BLOCKS = NHEAT / (THREADS * 4);           // 256
constexpr int PRE_BLOCKS   = FOCAL_BLOCKS + 1;                // focal + reg first
constexpr int TOTAL_BLOCKS = PRE_BLOCKS + OHEM_BLOCKS;        // 2305

// ---------------- device accumulators (zero at load; final block re-zeros
// them each run so graph replays stay deterministic) ----------------
__device__ double             g_sum_hard;
__device__ unsigned long long g_cnt_hard;
__device__ unsigned long long g_cnt_valid;
__device__ double             g_hist_sum[NBINS];
__device__ unsigned int       g_hist_cnt[NBINS];
__device__ double             g_pos_loss;
__device__ double             g_neg_loss;
__device__ double             g_npos;
__device__ double             g_reg_sum;
__device__ unsigned int       g_done;

__device__ __forceinline__ float ex2f(float x) {
    float r;
    asm("ex2.approx.ftz.f32 %0, %1;" : "=f"(r) : "f"(x));
    return r;
}
__device__ __forceinline__ float lg2f(float x) {
    float r;
    asm("lg2.approx.ftz.f32 %0, %1;" : "=f"(r) : "f"(x));
    return r;
}

// ---------------- one fused kernel ----------------
__global__ __launch_bounds__(THREADS, 5) void fused_loss_kernel(
    const float* __restrict__ seg,     const int*   __restrict__ masks,
    const float* __restrict__ hm_pred, const float* __restrict__ hm_tgt,
    const float* __restrict__ wh,      const float* __restrict__ bboxes,
    const int*   __restrict__ ct,      float* __restrict__ out)
{
    const int bid  = blockIdx.x;
    const int tid  = threadIdx.x;
    const int lane = tid & 31, wid = tid >> 5;

    __shared__ float    s_f0[8], s_f1[8], s_f2[8];
    __shared__ unsigned s_u0[8], s_u1[8];

    if (bid >= PRE_BLOCKS) {
        // === OHEM CE: 8 pixels/thread (2 float4 beats), streaming softmax ===
        int ob   = bid - PRE_BLOCKS;
        int b    = ob >> 8;                    // / TILES_PER_IMG
        int tile = ob & (TILES_PER_IMG - 1);
        // thread's first quad: quads laid out [tile][beat][thread]
        int q0 = tile * (TILE_PIX / 4) + tid;          // beat 0 quad index in image
        const float* img = seg + (size_t)b * C * HW;
        const float4* base4 = (const float4*)img;

        int4 ta = __ldcs((const int4*)masks + (size_t)b * (HW / 4) + q0);
        int4 tb = __ldcs((const int4*)masks + (size_t)b * (HW / 4) + q0 + THREADS);

        float sA0 = 0.f, sA1 = 0.f, sA2 = 0.f, sA3 = 0.f;
        float sB0 = 0.f, sB1 = 0.f, sB2 = 0.f, sB3 = 0.f;
        float xA0 = 0.f, xA1 = 0.f, xA2 = 0.f, xA3 = 0.f;
        float xB0 = 0.f, xB1 = 0.f, xB2 = 0.f, xB3 = 0.f;
        #pragma unroll
        for (int c = 0; c < C; c++) {
            float4 va = __ldcs(base4 + (size_t)c * (HW / 4) + q0);
            float4 vb = __ldcs(base4 + (size_t)c * (HW / 4) + q0 + THREADS);
            sA0 += ex2f(va.x * L2E);  sA1 += ex2f(va.y * L2E);
            sA2 += ex2f(va.z * L2E);  sA3 += ex2f(va.w * L2E);
            sB0 += ex2f(vb.x * L2E);  sB1 += ex2f(vb.y * L2E);
            sB2 += ex2f(vb.z * L2E);  sB3 += ex2f(vb.w * L2E);
            xA0 = (c == ta.x) ? va.x : xA0;  xA1 = (c == ta.y) ? va.y : xA1;
            xA2 = (c == ta.z) ? va.z : xA2;  xA3 = (c == ta.w) ? va.w : xA3;
            xB0 = (c == tb.x) ? vb.x : xB0;  xB1 = (c == tb.y) ? vb.y : xB1;
            xB2 = (c == tb.z) ? vb.z : xB2;  xB3 = (c == tb.w) ? vb.w : xB3;
        }

        float ce[8];
        ce[0] = (ta.x != 255) ? __fmaf_rn(lg2f(sA0), LN2, -xA0) : 0.0f;
        ce[1] = (ta.y != 255) ? __fmaf_rn(lg2f(sA1), LN2, -xA1) : 0.0f;
        ce[2] = (ta.z != 255) ? __fmaf_rn(lg2f(sA2), LN2, -xA2) : 0.0f;
        ce[3] = (ta.w != 255) ? __fmaf_rn(lg2f(sA3), LN2, -xA3) : 0.0f;
        ce[4] = (tb.x != 255) ? __fmaf_rn(lg2f(sB0), LN2, -xB0) : 0.0f;
        ce[5] = (tb.y != 255) ? __fmaf_rn(lg2f(sB1), LN2, -xB1) : 0.0f;
        ce[6] = (tb.z != 255) ? __fmaf_rn(lg2f(sB2), LN2, -xB2) : 0.0f;
        ce[7] = (tb.w != 255) ? __fmaf_rn(lg2f(sB3), LN2, -xB3) : 0.0f;
        unsigned vmask = (unsigned)(ta.x != 255) + (unsigned)(ta.y != 255)
                       + (unsigned)(ta.z != 255) + (unsigned)(ta.w != 255)
                       + (unsigned)(tb.x != 255) + (unsigned)(tb.y != 255)
                       + (unsigned)(tb.z != 255) + (unsigned)(tb.w != 255);

        float fs = 0.0f; unsigned hc = 0;
        #pragma unroll
        for (int k = 0; k < 8; k++) {
            bool hk = ce[k] > OHEM_THRESH;
            fs += hk ? ce[k] : 0.0f;
            hc += (unsigned)hk;
            if (!hk) {   // rare: histogram (expected ~handful of hits total)
                int bin = min(max((int)(ce[k] * BIN_SCALE), 0), NBINS - 1);
                atomicAdd(&g_hist_cnt[bin], 1u);
                atomicAdd(&g_hist_sum[bin], (double)ce[k]);
            }
        }
        unsigned vc = vmask;

        #pragma unroll
        for (int o = 16; o > 0; o >>= 1) {
            fs += __shfl_xor_sync(0xffffffffu, fs, o);
            hc += __shfl_xor_sync(0xffffffffu, hc, o);
            vc += __shfl_xor_sync(0xffffffffu, vc, o);
        }
        if (lane == 0) { s_f0[wid] = fs; s_u0[wid] = hc; s_u1[wid] = vc; }
        __syncthreads();
        if (tid == 0) {
            double ts = 0.0; unsigned th = 0, tv = 0;
            #pragma unroll
            for (int i = 0; i < 8; i++) { ts += (double)s_f0[i]; th += s_u0[i]; tv += s_u1[i]; }
            atomicAdd(&g_sum_hard, ts);
            atomicAdd(&g_cnt_hard, (unsigned long long)th);
            atomicAdd(&g_cnt_valid, (unsigned long long)tv);
        }
    } else if (bid < FOCAL_BLOCKS) {
        // ============ focal: 4 elems per thread via float4 ============
        int i4 = bid * THREADS + tid;
        float4 pv  = __ldcs((const float4*)hm_pred + i4);
        float4 tv4 = __ldcs((const float4*)hm_tgt + i4);

        float pl = 0.0f, nl = 0.0f, np = 0.0f;
        const float* pp = &pv.x;
        const float* tp = &tv4.x;
        #pragma unroll
        for (int k = 0; k < 4; k++) {
            float p = fmaxf(pp[k], F32_TINY);
            float t = tp[k];
            if (t == 1.0f) {
                float om = 1.0f - p;
                pl += lg2f(p) * LN2 * om * om;
                np += 1.0f;
            } else {
                float omt = 1.0f - t;
                float wgt = omt * omt; wgt *= wgt;
                nl += lg2f(1.0f - p + F32_TINY) * LN2 * p * p * wgt;
            }
        }
        #pragma unroll
        for (int o = 16; o > 0; o >>= 1) {
            pl += __shfl_xor_sync(0xffffffffu, pl, o);
            nl += __shfl_xor_sync(0xffffffffu, nl, o);
            np += __shfl_xor_sync(0xffffffffu, np, o);
        }
        if (lane == 0) { s_f0[wid] = pl; s_f1[wid] = nl; s_f2[wid] = np; }
        __syncthreads();
        if (tid == 0) {
            double tpd = 0, tnd = 0, tcd = 0;
            #pragma unroll
            for (int k = 0; k < 8; k++) { tpd += (double)s_f0[k]; tnd += (double)s_f1[k]; tcd += (double)s_f2[k]; }
            atomicAdd(&g_pos_loss, tpd);
            atomicAdd(&g_neg_loss, tnd);
            atomicAdd(&g_npos, tcd);
        }
    } else {
        // ============ L1 regression (512 boxes, 2 per thread) ============
        float l1 = 0.0f;
        #pragma unroll
        for (int r = 0; r < 2; r++) {
            int i = tid + r * THREADS;
            int b = i >> 6;
            int x = ct[i * 2 + 0];
            int y = ct[i * 2 + 1];
            const float* whb = wh + (size_t)b * 2 * HhWh;
            float v0 = whb[y * Wh + x];
            float v1 = whb[HhWh + y * Wh + x];
            const float* bb = bboxes + (size_t)i * 4;
            float w = bb[2] - bb[0];
            float h = bb[3] - bb[1];
            l1 += fabsf(v0 - w) + fabsf(v1 - h);
        }
        #pragma unroll
        for (int o = 16; o > 0; o >>= 1) l1 += __shfl_xor_sync(0xffffffffu, l1, o);
        if (lane == 0) s_f0[wid] = l1;
        __syncthreads();
        if (tid == 0) {
            double tot = 0.0;
            #pragma unroll
            for (int k = 0; k < 8; k++) tot += (double)s_f0[k];
            g_reg_sum = tot;
        }
    }

    // ===================== last-block election =====================
    __shared__ bool s_last;
    __syncthreads();
    if (tid == 0) {
        __threadfence();
        unsigned prev = atomicAdd(&g_done, 1u);
        s_last = (prev == (unsigned)(TOTAL_BLOCKS - 1));
    }
    __syncthreads();
    if (!s_last) return;
    __threadfence();

    __shared__ float s_out[4];
    if (tid == 0) {
        // classification (OHEM)
        unsigned long long nmin = g_cnt_valid / 16ull;
        double k, top;
        if (g_cnt_hard >= nmin) {
            k = (double)g_cnt_hard;
            top = g_sum_hard;
        } else {
            k = (double)nmin;
            top = g_sum_hard;
            double need = (double)(nmin - g_cnt_hard);
            for (int bin = NBINS - 1; bin >= 0 && need > 0.0; --bin) {
                unsigned c = g_hist_cnt[bin];
                if (!c) continue;
                if ((double)c <= need) { top += g_hist_sum[bin]; need -= (double)c; }
                else                   { top += g_hist_sum[bin] * (need / (double)c); need = 0.0; }
            }
        }
        float cls = (k > 0.0) ? (float)(top / k) : 0.0f;

        // centerness (focal)
        double npos = g_npos;
        double fl = (npos == 0.0) ? -g_neg_loss
                                  : -(g_pos_loss + g_neg_loss) / fmax(npos, 1.0);
        float centerness = (float)fl;

        // bbox
        float regression = (float)g_reg_sum * 0.7f;
        float bbox = regression / ((float)NBOX + 1e-7f) * 0.1f;
        float localization = (centerness + bbox) * 1.0f;

        s_out[0] = cls;
        s_out[1] = localization;
        s_out[2] = centerness;
        s_out[3] = bbox;
    }
    __syncthreads();

    if (tid < 4) out[tid] = s_out[tid];
    for (int bin = tid; bin < NBINS; bin += THREADS) {
        g_hist_sum[bin] = 0.0;
        g_hist_cnt[bin] = 0u;
    }
    if (tid == 0) {
        g_sum_hard = 0.0; g_cnt_hard = 0ull; g_cnt_valid = 0ull;
        g_pos_loss = 0.0; g_neg_loss = 0.0; g_npos = 0.0; g_reg_sum = 0.0;
        __threadfence();
        g_done = 0u;
    }
}

// ---------------- launch ----------------
extern "C" void kernel_launch(void* const* d_in, const int* in_sizes, int n_in,
                              void* d_out, int out_size)
{
    const float* seg     = (const float*)d_in[0];
    const int*   masks   = (const int*)  d_in[1];
    const float* hm_pred = (const float*)d_in[2];
    const float* hm_tgt  = (const float*)d_in[3];
    const float* wh      = (const float*)d_in[4];
    const float* bboxes  = (const float*)d_in[5];
    // d_in[6] = labels (unused by the reference loss)
    const int*   ct      = (const int*)  d_in[7];
    float* out = (float*)d_out;

    fused_loss_kernel<<<TOTAL_BLOCKS, THREADS>>>(
        seg, masks, hm_pred, hm_tgt, wh, bboxes, ct, out);
}